// round 15
// baseline (speedup 1.0000x reference)
#include <cuda_runtime.h>
#include <math.h>

// ---------------- problem constants (fixed shapes) ----------------
#define B_      2
#define N_      6
#define CAMS    (B_ * N_)          // 12
#define CAM_C   256
#define OUT_C   64
#define D_BINS  59
#define M_FEAT  (D_BINS + OUT_C)   // 123
#define FH      16
#define FW      44
#define HW      (FH * FW)          // 704
#define NX      128
#define NY      128
#define NCELL   (NX * NY)          // 16384 (NZ = 1)

// tile: 2 image columns x 16 rows = 32 pixels. np = wl*16 + h
#define WCOLS   2
#define BM 128
#define BN 32
#define BK 32
#define NCHUNK (CAM_C / BK)              // 8
#define NTHREADS 256
#define NBLOCKS  ((FW / WCOLS) * CAMS)   // 264

#define WS_STRIDE 130
#define XS_STRIDE 36
#define DS_STRIDE 61
#define CS_STRIDE 68

#define BUF_FLOATS (BK * WS_STRIDE + BK * XS_STRIDE)   // 5312 per buffer
#define SMEM_FLOATS (2 * BUF_FLOATS)                   // 10624 = 42.5 KB

#define SCR_SZ (B_ * NCELL * OUT_C)   // 2M floats = 8 MB per buffer
#define NTILES (B_ * NCELL / 64)      // 512 transpose tiles of 64 cells

typedef unsigned long long ull;

// ping-pong scratch: buffer (ep&1) is active this launch (pre-zeroed by the
// previous launch's transpose kernel); buffer (ep+1)&1 is zeroed during THIS
// launch's transpose kernel. Both zero at module load.
__device__ float g_scratch[2 * SCR_SZ];   // 16 MB
// monotonic ticket counter for epoch bump (never reset; replay-safe)
__device__ int g_cnt_tr;
// launch epoch: read by both kernels, incremented by last transpose block
__device__ int g_epoch;

// ------------- kernel 1: GEMM + softmax + scatter (posts reds) -------------
__global__ __launch_bounds__(NTHREADS, 2)
void lss_fused_kernel(const float* __restrict__ x,
                      const float* __restrict__ rots,
                      const float* __restrict__ trans,
                      const float* __restrict__ intrins,
                      const float* __restrict__ depth_w,
                      const float* __restrict__ depth_b)
{
    __shared__ __align__(16) float smem[SMEM_FLOATS];
    __shared__ float comb[9];
    __shared__ float tr[3];
    __shared__ int   s_fast;
    __shared__ int   s_ep;

    const int cam = blockIdx.y;             // 0..11
    const int b   = cam / N_;
    const int w0  = blockIdx.x * WCOLS;     // image-column pair start
    const int tid = threadIdx.x;
    const int tm  = tid >> 3;               // 0..31 -> 4 M-rows (2 even pairs)
    const int tn  = tid & 7;                // 0..7  -> 4 pixels

    // --- epoch read + geometry setup (thread 0) ---
    if (tid == 0) {
        s_ep = *(volatile int*)&g_epoch;    // stable: writer ran last launch

        const float* R = rots    + cam * 9;
        const float* K = intrins + cam * 9;
        float a = K[0], bb = K[1], c = K[2];
        float d = K[3], e  = K[4], f = K[5];
        float g = K[6], h  = K[7], i = K[8];
        float A  = e * i - f * h;
        float Bv = -(d * i - f * g);
        float Cv = d * h - e * g;
        float id = 1.0f / (a * A + bb * Bv + c * Cv);
        float inv[9];
        inv[0] = A * id;  inv[1] = (c * h - bb * i) * id; inv[2] = (bb * f - c * e) * id;
        inv[3] = Bv * id; inv[4] = (a * i - c * g) * id;  inv[5] = (c * d - a * f) * id;
        inv[6] = Cv * id; inv[7] = (bb * g - a * h) * id; inv[8] = (a * e - bb * d) * id;
        #pragma unroll
        for (int r = 0; r < 3; r++)
            #pragma unroll
            for (int col = 0; col < 3; col++)
                comb[r * 3 + col] = R[r * 3 + 0] * inv[0 + col]
                                  + R[r * 3 + 1] * inv[3 + col]
                                  + R[r * 3 + 2] * inv[6 + col];
        tr[0] = trans[cam * 3 + 0];
        tr[1] = trans[cam * 3 + 1];
        tr[2] = trans[cam * 3 + 2];
        // fast path: gx, gy independent of image row (exact zeros)
        s_fast = (comb[1] == 0.0f) && (comb[4] == 0.0f);
    }

    // --- phase 1: feat = W @ x, FFMA2, double-buffered smem chunks ---
    ull acc[2][4];                           // [M-pair][pixel]
    #pragma unroll
    for (int i4 = 0; i4 < 2; i4++)
        #pragma unroll
        for (int j = 0; j < 4; j++) acc[i4][j] = 0ull;

    const float* xcam = x + (size_t)cam * CAM_C * HW;

    float wreg[16];   // BM*BK/NTHREADS
    float xreg[4];    // BK*BN/NTHREADS

    // prologue: load chunk 0 into registers, publish to buf0
    #pragma unroll
    for (int it = 0; it < 16; it++) {
        int idx = it * NTHREADS + tid;
        int m   = idx >> 5;
        int kk  = idx & 31;
        wreg[it] = (m < M_FEAT) ? depth_w[m * CAM_C + kk] : 0.f;
    }
    #pragma unroll
    for (int it = 0; it < 4; it++) {
        int idx = it * NTHREADS + tid;
        int kk  = idx >> 5;
        int sub = idx & 31;
        int wl  = sub & 1;
        int h   = sub >> 1;
        xreg[it] = xcam[(size_t)kk * HW + h * FW + w0 + wl];
    }
    {
        float* Ws0 = smem;
        float* Xs0 = smem + BK * WS_STRIDE;
        #pragma unroll
        for (int it = 0; it < 16; it++) {
            int idx = it * NTHREADS + tid;
            int m   = idx >> 5;
            int kk  = idx & 31;
            Ws0[kk * WS_STRIDE + m] = wreg[it];
        }
        #pragma unroll
        for (int it = 0; it < 4; it++) {
            int idx = it * NTHREADS + tid;
            int kk  = idx >> 5;
            int sub = idx & 31;
            int wl  = sub & 1;
            int h   = sub >> 1;
            Xs0[kk * XS_STRIDE + wl * 16 + h] = xreg[it];
        }
    }
    // prefetch chunk 1 into registers while buf0 publishes
    #pragma unroll
    for (int it = 0; it < 16; it++) {
        int idx = it * NTHREADS + tid;
        int m   = idx >> 5;
        int kk  = idx & 31;
        wreg[it] = (m < M_FEAT) ? depth_w[m * CAM_C + BK + kk] : 0.f;
    }
    #pragma unroll
    for (int it = 0; it < 4; it++) {
        int idx = it * NTHREADS + tid;
        int kk  = idx >> 5;
        int sub = idx & 31;
        int wl  = sub & 1;
        int h   = sub >> 1;
        xreg[it] = xcam[(size_t)(BK + kk) * HW + h * FW + w0 + wl];
    }
    __syncthreads();   // buf0 visible

    for (int c = 0; c < NCHUNK; c++) {
        const float* Wsb = smem + (c & 1) * BUF_FLOATS;
        const float* Xsb = Wsb + BK * WS_STRIDE;

        // compute chunk c: 2 LDS.64 (W) + 1 LDS.128 (X) per kk
        #pragma unroll 4
        for (int kk = 0; kk < BK; kk++) {
            ull wp[2];
            #pragma unroll
            for (int i4 = 0; i4 < 2; i4++)
                wp[i4] = *(const ull*)&Wsb[kk * WS_STRIDE + tm * 4 + 2 * i4];
            float4 xv = *(const float4*)&Xsb[kk * XS_STRIDE + tn * 4];
            ull xd[4];
            asm("mov.b64 %0, {%1, %1};" : "=l"(xd[0]) : "f"(xv.x));
            asm("mov.b64 %0, {%1, %1};" : "=l"(xd[1]) : "f"(xv.y));
            asm("mov.b64 %0, {%1, %1};" : "=l"(xd[2]) : "f"(xv.z));
            asm("mov.b64 %0, {%1, %1};" : "=l"(xd[3]) : "f"(xv.w));
            #pragma unroll
            for (int i4 = 0; i4 < 2; i4++)
                #pragma unroll
                for (int j = 0; j < 4; j++)
                    asm("fma.rn.f32x2 %0, %1, %2, %0;"
                        : "+l"(acc[i4][j]) : "l"(wp[i4]), "l"(xd[j]));
        }

        if (c + 1 < NCHUNK) {
            // publish prefetched chunk c+1 into the OTHER buffer
            float* Wn = smem + ((c + 1) & 1) * BUF_FLOATS;
            float* Xn = Wn + BK * WS_STRIDE;
            #pragma unroll
            for (int it = 0; it < 16; it++) {
                int idx = it * NTHREADS + tid;
                int m   = idx >> 5;
                int kk  = idx & 31;
                Wn[kk * WS_STRIDE + m] = wreg[it];
            }
            #pragma unroll
            for (int it = 0; it < 4; it++) {
                int idx = it * NTHREADS + tid;
                int kk  = idx >> 5;
                int sub = idx & 31;
                int wl  = sub & 1;
                int h   = sub >> 1;
                Xn[kk * XS_STRIDE + wl * 16 + h] = xreg[it];
            }
            // prefetch chunk c+2 into registers
            if (c + 2 < NCHUNK) {
                int kc = (c + 2) * BK;
                #pragma unroll
                for (int it = 0; it < 16; it++) {
                    int idx = it * NTHREADS + tid;
                    int m   = idx >> 5;
                    int kk  = idx & 31;
                    wreg[it] = (m < M_FEAT) ? depth_w[m * CAM_C + kc + kk] : 0.f;
                }
                #pragma unroll
                for (int it = 0; it < 4; it++) {
                    int idx = it * NTHREADS + tid;
                    int kk  = idx >> 5;
                    int sub = idx & 31;
                    int wl  = sub & 1;
                    int h   = sub >> 1;
                    xreg[it] = xcam[(size_t)(kc + kk) * HW + h * FW + w0 + wl];
                }
            }
            __syncthreads();   // single sync per chunk
        }
    }
    // phase 2 writes only buf0 sub-region, disjoint from buf1 (chunk 7) reads.

    // --- phase 2: unpack accs (+bias) into depthS / ctxS ---
    float* depthS = smem;                     // [np][61]
    float* ctxS   = smem + BN * DS_STRIDE;    // [np][68]

    #pragma unroll
    for (int i4 = 0; i4 < 2; i4++) {
        int m0 = tm * 4 + 2 * i4;
        float b0 = (m0     < M_FEAT) ? depth_b[m0]     : 0.f;
        float b1 = (m0 + 1 < M_FEAT) ? depth_b[m0 + 1] : 0.f;
        #pragma unroll
        for (int j = 0; j < 4; j++) {
            float lo, hi;
            asm("mov.b64 {%0, %1}, %2;" : "=f"(lo), "=f"(hi) : "l"(acc[i4][j]));
            int pix = tn * 4 + j;
            float v0 = lo + b0, v1 = hi + b1;
            if (m0 < D_BINS)       depthS[pix * DS_STRIDE + m0] = v0;
            else if (m0 < M_FEAT)  ctxS[pix * CS_STRIDE + (m0 - D_BINS)] = v0;
            int m1 = m0 + 1;
            if (m1 < D_BINS)       depthS[pix * DS_STRIDE + m1] = v1;
            else if (m1 < M_FEAT)  ctxS[pix * CS_STRIDE + (m1 - D_BINS)] = v1;
        }
    }
    __syncthreads();

    const float c00 = comb[0], c01 = comb[1], c02 = comb[2];
    const float c10 = comb[3], c11 = comb[4], c12 = comb[5];
    const float c20 = comb[6], c21 = comb[7], c22 = comb[8];
    const float t0 = tr[0], t1 = tr[1], t2 = tr[2];
    const float xstep = 703.0f / 43.0f;
    const float ystep = 255.0f / 15.0f;
    const int   fast  = s_fast;
    const int   ep    = s_ep;

    // --- softmax: 8 lanes per pixel, shfl reductions; zero z-invalid bins ---
    {
        int pix = tid >> 3;          // 0..31
        int sub = tid & 7;           // 0..7
        float* row = depthS + pix * DS_STRIDE;

        float mx = -1e30f;
        for (int d = sub; d < D_BINS; d += 8) mx = fmaxf(mx, row[d]);
        #pragma unroll
        for (int o = 1; o < 8; o <<= 1)
            mx = fmaxf(mx, __shfl_xor_sync(0xffffffffu, mx, o));

        float s = 0.f;
        for (int d = sub; d < D_BINS; d += 8) {
            float e = __expf(row[d] - mx);
            row[d] = e;
            s += e;
        }
        #pragma unroll
        for (int o = 1; o < 8; o <<= 1)
            s += __shfl_xor_sync(0xffffffffu, s, o);
        float invs = 1.0f / s;

        if (fast) {
            int wl = pix >> 4, h = pix & 15;
            float xim = (float)(w0 + wl) * xstep;
            float yim = (float)h * ystep;
            for (int d = sub; d < D_BINS; d += 8) {
                float ds = 1.0f + (float)d;
                float gz = c20 * (xim * ds) + c21 * (yim * ds) + c22 * ds + t2;
                int cz = (int)floorf((gz + 10.0f) / 20.0f);
                row[d] = (cz == 0) ? row[d] * invs : 0.f;
            }
        } else {
            for (int d = sub; d < D_BINS; d += 8) row[d] *= invs;
        }
    }
    __syncthreads();   // publish softmax; active buffer pre-zeroed last launch

    float* base = g_scratch + (size_t)(ep & 1) * SCR_SZ
                            + (size_t)b * NCELL * OUT_C;

    if (fast) {
        // --- fast combine+scatter: warp = (wl, 16-depth chunk);
        //     lane = (dloc, channel-half). ctx broadcast, accs in registers.
        const int warp  = tid >> 5;           // 0..7
        const int lane  = tid & 31;
        const int wl    = warp & 1;
        const int d0    = (warp >> 1) * 16;   // 0,16,32,48
        const int dloc  = lane >> 1;          // 0..15
        const int d     = d0 + dloc;
        const int chalf = lane & 1;           // channels chalf*32 .. +31
        const bool dok  = (d < D_BINS);

        float ds  = 1.0f + (float)d;
        float xim = (float)(w0 + wl) * xstep;
        float gx = c00 * (xim * ds) + c02 * ds + t0;   // c01 exactly 0
        float gy = c10 * (xim * ds) + c12 * ds + t1;   // c11 exactly 0
        int cx = (int)floorf((gx + 51.2f) / 0.8f);
        int cy = (int)floorf((gy + 51.2f) / 0.8f);
        bool ok = dok && ((unsigned)cx < (unsigned)NX) && ((unsigned)cy < (unsigned)NY);

        ull v[16];                              // 8 float4 accumulators
        #pragma unroll
        for (int j = 0; j < 16; j++) v[j] = 0ull;
        float dwsum = 0.f;

        const float* drow0 = depthS + (wl * 16) * DS_STRIDE;
        const float* crow0 = ctxS   + (wl * 16) * CS_STRIDE + chalf * 32;

        #pragma unroll
        for (int h = 0; h < 16; h++) {
            float dw = dok ? drow0[h * DS_STRIDE + d] : 0.f;
            dwsum += dw;
            ull dw2; asm("mov.b64 %0, {%1, %1};" : "=l"(dw2) : "f"(dw));
            const float* cr = crow0 + h * CS_STRIDE;
            #pragma unroll
            for (int q = 0; q < 8; q++) {
                float4 cc = *(const float4*)(cr + q * 4);   // warp-broadcast
                ull lo, hi;
                asm("mov.b64 %0, {%1, %2};" : "=l"(lo) : "f"(cc.x), "f"(cc.y));
                asm("mov.b64 %0, {%1, %2};" : "=l"(hi) : "f"(cc.z), "f"(cc.w));
                asm("fma.rn.f32x2 %0, %1, %2, %0;" : "+l"(v[2*q  ]) : "l"(lo), "l"(dw2));
                asm("fma.rn.f32x2 %0, %1, %2, %0;" : "+l"(v[2*q+1]) : "l"(hi), "l"(dw2));
            }
        }

        if (ok && dwsum != 0.f) {
            float* dst = base + ((size_t)cy * NX + cx) * OUT_C + chalf * 32;
            #pragma unroll
            for (int q = 0; q < 8; q++) {
                float f0, f1, f2, f3;
                asm("mov.b64 {%0, %1}, %2;" : "=f"(f0), "=f"(f1) : "l"(v[2*q  ]));
                asm("mov.b64 {%0, %1}, %2;" : "=f"(f2), "=f"(f3) : "l"(v[2*q+1]));
                asm volatile("red.global.add.v4.f32 [%0], {%1, %2, %3, %4};"
                             :: "l"(dst + q * 4),
                                "f"(f0), "f"(f1), "f"(f2), "f"(f3) : "memory");
            }
        }
    } else {
        // --- generic fallback: per-point scatter (any geometry) ---
        for (int idx = tid; idx < BN * D_BINS; idx += NTHREADS) {
            int np = idx / D_BINS;
            int d  = idx - np * D_BINS;
            int wl = np >> 4, h = np & 15;
            float ds  = 1.0f + (float)d;
            float xim = (float)(w0 + wl) * xstep;
            float yim = (float)h * ystep;
            float px = xim * ds, py = yim * ds, pz = ds;
            float gx = c00 * px + c01 * py + c02 * pz + t0;
            float gy = c10 * px + c11 * py + c12 * pz + t1;
            float gz = c20 * px + c21 * py + c22 * pz + t2;
            int cx = (int)floorf((gx + 51.2f) / 0.8f);
            int cy = (int)floorf((gy + 51.2f) / 0.8f);
            int cz = (int)floorf((gz + 10.0f) / 20.0f);
            if (((unsigned)cx < (unsigned)NX) && ((unsigned)cy < (unsigned)NY) && cz == 0) {
                float dwgt = depthS[np * DS_STRIDE + d];
                float* dst = base + ((size_t)cy * NX + cx) * OUT_C;
                const float4* cv = (const float4*)(ctxS + np * CS_STRIDE);
                #pragma unroll
                for (int c4 = 0; c4 < OUT_C / 4; c4++) {
                    float4 v = cv[c4];
                    asm volatile("red.global.add.v4.f32 [%0], {%1, %2, %3, %4};"
                                 :: "l"(dst + c4 * 4),
                                    "f"(v.x * dwgt), "f"(v.y * dwgt),
                                    "f"(v.z * dwgt), "f"(v.w * dwgt) : "memory");
                }
            }
        }
    }
    // kernel ends: reds drain behind the kernel boundary; the next kernel in
    // the stream observes them (CUDA kernel-boundary ordering).
}

// ------------- kernel 2: transpose + zero-other + epoch bump ---------------
__global__ __launch_bounds__(256, 4)
void transpose_bev_kernel(float* __restrict__ out)
{
    __shared__ float tile[OUT_C][64 + 1];   // 64 x 65
    __shared__ int   s_ep;
    const int tid = threadIdx.x;            // 256
    const int t   = blockIdx.x;             // tile id 0..511

    if (tid == 0) s_ep = *(volatile int*)&g_epoch;
    __syncthreads();
    const int ep = s_ep;
    const float* scrA = g_scratch + (size_t)(ep & 1) * SCR_SZ;       // read
    float*       scrB = g_scratch + (size_t)((ep + 1) & 1) * SCR_SZ; // zero

    // zero this block's 1/512 slice of the next launch's buffer (cold lines)
    {
        float4* p = (float4*)scrB + (size_t)t * (SCR_SZ / 4 / NTILES);
        const float4 z4 = make_float4(0.f, 0.f, 0.f, 0.f);
        #pragma unroll
        for (int i = 0; i < (SCR_SZ / 4 / NTILES) / 256; i++)   // 4 per thread
            p[i * 256 + tid] = z4;
    }

    // transpose tile t: (B, cell, C) -> (B, C, cell)
    const int bz    = t >> 8;               // t / 256
    const int cell0 = (t & 255) * 64;
    #pragma unroll
    for (int i = 0; i < 4; i++) {
        int idx  = i * 256 + tid;           // 0..1023
        int cell = idx >> 4;
        int c4   = idx & 15;
        float4 v = *(const float4*)&scrA[
            ((size_t)bz * NCELL + cell0 + cell) * OUT_C + c4 * 4];
        tile[c4 * 4 + 0][cell] = v.x;
        tile[c4 * 4 + 1][cell] = v.y;
        tile[c4 * 4 + 2][cell] = v.z;
        tile[c4 * 4 + 3][cell] = v.w;
    }
    __syncthreads();
    #pragma unroll
    for (int i = 0; i < 4; i++) {
        int idx = i * 256 + tid;
        int ch  = idx >> 4;
        int seg = idx & 15;
        float4 v = make_float4(tile[ch][seg * 4 + 0], tile[ch][seg * 4 + 1],
                               tile[ch][seg * 4 + 2], tile[ch][seg * 4 + 3]);
        *(float4*)&out[((size_t)(bz * OUT_C + ch)) * NCELL + cell0 + seg * 4] = v;
    }

    // epoch bump: last block to take a ticket advances the epoch (monotonic,
    // replay-safe; all blocks read g_epoch before taking their ticket).
    if (tid == 0) {
        int tk = atomicAdd(&g_cnt_tr, 1);
        if ((tk % NTILES) == NTILES - 1)
            *(volatile int*)&g_epoch = ep + 1;
    }
}

// ---------------- launch ----------------
extern "C" void kernel_launch(void* const* d_in, const int* in_sizes, int n_in,
                              void* d_out, int out_size)
{
    const float* x       = (const float*)d_in[0];
    const float* rots    = (const float*)d_in[1];
    const float* trans   = (const float*)d_in[2];
    const float* intrins = (const float*)d_in[3];
    const float* depth_w = (const float*)d_in[4];
    const float* depth_b = (const float*)d_in[5];
    float* out = (float*)d_out;

    // kernel 1: GEMM + softmax + scatter (reds posted; drain over boundary)
    {
        dim3 grid(FW / WCOLS, CAMS);   // (22, 12) = 264 blocks
        lss_fused_kernel<<<grid, NTHREADS>>>(x, rots, trans, intrins,
                                             depth_w, depth_b);
    }
    // kernel 2: transpose to (B, C, NY, NX) + zero other buffer + epoch bump
    transpose_bev_kernel<<<NTILES, 256>>>(out);

    (void)in_sizes; (void)n_in; (void)out_size;
}

// round 16
// speedup vs baseline: 1.0060x; 1.0060x over previous
#include <cuda_runtime.h>
#include <math.h>

// ---------------- problem constants (fixed shapes) ----------------
#define B_      2
#define N_      6
#define CAMS    (B_ * N_)          // 12
#define CAM_C   256
#define OUT_C   64
#define D_BINS  59
#define M_FEAT  (D_BINS + OUT_C)   // 123
#define FH      16
#define FW      44
#define HW      (FH * FW)          // 704
#define NX      128
#define NY      128
#define NCELL   (NX * NY)          // 16384 (NZ = 1)

// tile: 2 image columns x 16 rows = 32 pixels. np = wl*16 + h
#define WCOLS   2
#define BM 128
#define BN 32
#define BK 32
#define NCHUNK (CAM_C / BK)              // 8
#define NTHREADS 256
#define NBLOCKS  ((FW / WCOLS) * CAMS)   // 264

#define WS_STRIDE 130
#define XS_STRIDE 36
#define DS_STRIDE 61
#define CS_STRIDE 68

#define BUF_FLOATS (BK * WS_STRIDE + BK * XS_STRIDE)   // 5312 per buffer
#define SMEM_FLOATS (2 * BUF_FLOATS)                   // 10624 = 42.5 KB

#define SCR_SZ (B_ * NCELL * OUT_C)   // 2M floats = 8 MB per buffer
#define TCELLS  32
#define NTILES (B_ * NCELL / TCELLS)  // 1024 transpose tiles of 32 cells

typedef unsigned long long ull;

// ping-pong scratch: buffer (ep&1) is active this launch (pre-zeroed by the
// previous launch's transpose kernel); buffer (ep+1)&1 is zeroed during THIS
// launch's transpose kernel. Both zero at module load.
__device__ float g_scratch[2 * SCR_SZ];   // 16 MB
// monotonic ticket counter for epoch bump (never reset; replay-safe)
__device__ int g_cnt_tr;
// launch epoch: read by both kernels, incremented by last transpose block
__device__ int g_epoch;

// ------------- kernel 1: GEMM + softmax + scatter (posts reds) -------------
__global__ __launch_bounds__(NTHREADS, 2)
void lss_fused_kernel(const float* __restrict__ x,
                      const float* __restrict__ rots,
                      const float* __restrict__ trans,
                      const float* __restrict__ intrins,
                      const float* __restrict__ depth_w,
                      const float* __restrict__ depth_b)
{
    __shared__ __align__(16) float smem[SMEM_FLOATS];
    __shared__ float comb[9];
    __shared__ float tr[3];
    __shared__ int   s_fast;
    __shared__ int   s_ep;

    const int cam = blockIdx.y;             // 0..11
    const int b   = cam / N_;
    const int w0  = blockIdx.x * WCOLS;     // image-column pair start
    const int tid = threadIdx.x;
    const int tm  = tid >> 3;               // 0..31 -> 4 M-rows (2 even pairs)
    const int tn  = tid & 7;                // 0..7  -> 4 pixels

    // --- epoch read + geometry setup (thread 0) ---
    if (tid == 0) {
        s_ep = *(volatile int*)&g_epoch;    // stable: writer ran last launch

        const float* R = rots    + cam * 9;
        const float* K = intrins + cam * 9;
        float a = K[0], bb = K[1], c = K[2];
        float d = K[3], e  = K[4], f = K[5];
        float g = K[6], h  = K[7], i = K[8];
        float A  = e * i - f * h;
        float Bv = -(d * i - f * g);
        float Cv = d * h - e * g;
        float id = 1.0f / (a * A + bb * Bv + c * Cv);
        float inv[9];
        inv[0] = A * id;  inv[1] = (c * h - bb * i) * id; inv[2] = (bb * f - c * e) * id;
        inv[3] = Bv * id; inv[4] = (a * i - c * g) * id;  inv[5] = (c * d - a * f) * id;
        inv[6] = Cv * id; inv[7] = (bb * g - a * h) * id; inv[8] = (a * e - bb * d) * id;
        #pragma unroll
        for (int r = 0; r < 3; r++)
            #pragma unroll
            for (int col = 0; col < 3; col++)
                comb[r * 3 + col] = R[r * 3 + 0] * inv[0 + col]
                                  + R[r * 3 + 1] * inv[3 + col]
                                  + R[r * 3 + 2] * inv[6 + col];
        tr[0] = trans[cam * 3 + 0];
        tr[1] = trans[cam * 3 + 1];
        tr[2] = trans[cam * 3 + 2];
        // fast path: gx, gy independent of image row (exact zeros)
        s_fast = (comb[1] == 0.0f) && (comb[4] == 0.0f);
    }

    // --- phase 1: feat = W @ x, FFMA2, double-buffered smem chunks ---
    ull acc[2][4];                           // [M-pair][pixel]
    #pragma unroll
    for (int i4 = 0; i4 < 2; i4++)
        #pragma unroll
        for (int j = 0; j < 4; j++) acc[i4][j] = 0ull;

    const float* xcam = x + (size_t)cam * CAM_C * HW;

    float wreg[16];   // BM*BK/NTHREADS
    float xreg[4];    // BK*BN/NTHREADS

    // prologue: load chunk 0 into registers, publish to buf0
    #pragma unroll
    for (int it = 0; it < 16; it++) {
        int idx = it * NTHREADS + tid;
        int m   = idx >> 5;
        int kk  = idx & 31;
        wreg[it] = (m < M_FEAT) ? depth_w[m * CAM_C + kk] : 0.f;
    }
    #pragma unroll
    for (int it = 0; it < 4; it++) {
        int idx = it * NTHREADS + tid;
        int kk  = idx >> 5;
        int sub = idx & 31;
        int wl  = sub & 1;
        int h   = sub >> 1;
        xreg[it] = xcam[(size_t)kk * HW + h * FW + w0 + wl];
    }
    {
        float* Ws0 = smem;
        float* Xs0 = smem + BK * WS_STRIDE;
        #pragma unroll
        for (int it = 0; it < 16; it++) {
            int idx = it * NTHREADS + tid;
            int m   = idx >> 5;
            int kk  = idx & 31;
            Ws0[kk * WS_STRIDE + m] = wreg[it];
        }
        #pragma unroll
        for (int it = 0; it < 4; it++) {
            int idx = it * NTHREADS + tid;
            int kk  = idx >> 5;
            int sub = idx & 31;
            int wl  = sub & 1;
            int h   = sub >> 1;
            Xs0[kk * XS_STRIDE + wl * 16 + h] = xreg[it];
        }
    }
    // prefetch chunk 1 into registers while buf0 publishes
    #pragma unroll
    for (int it = 0; it < 16; it++) {
        int idx = it * NTHREADS + tid;
        int m   = idx >> 5;
        int kk  = idx & 31;
        wreg[it] = (m < M_FEAT) ? depth_w[m * CAM_C + BK + kk] : 0.f;
    }
    #pragma unroll
    for (int it = 0; it < 4; it++) {
        int idx = it * NTHREADS + tid;
        int kk  = idx >> 5;
        int sub = idx & 31;
        int wl  = sub & 1;
        int h   = sub >> 1;
        xreg[it] = xcam[(size_t)(BK + kk) * HW + h * FW + w0 + wl];
    }
    __syncthreads();   // buf0 visible

    for (int c = 0; c < NCHUNK; c++) {
        const float* Wsb = smem + (c & 1) * BUF_FLOATS;
        const float* Xsb = Wsb + BK * WS_STRIDE;

        // compute chunk c: 2 LDS.64 (W) + 1 LDS.128 (X) per kk
        #pragma unroll 4
        for (int kk = 0; kk < BK; kk++) {
            ull wp[2];
            #pragma unroll
            for (int i4 = 0; i4 < 2; i4++)
                wp[i4] = *(const ull*)&Wsb[kk * WS_STRIDE + tm * 4 + 2 * i4];
            float4 xv = *(const float4*)&Xsb[kk * XS_STRIDE + tn * 4];
            ull xd[4];
            asm("mov.b64 %0, {%1, %1};" : "=l"(xd[0]) : "f"(xv.x));
            asm("mov.b64 %0, {%1, %1};" : "=l"(xd[1]) : "f"(xv.y));
            asm("mov.b64 %0, {%1, %1};" : "=l"(xd[2]) : "f"(xv.z));
            asm("mov.b64 %0, {%1, %1};" : "=l"(xd[3]) : "f"(xv.w));
            #pragma unroll
            for (int i4 = 0; i4 < 2; i4++)
                #pragma unroll
                for (int j = 0; j < 4; j++)
                    asm("fma.rn.f32x2 %0, %1, %2, %0;"
                        : "+l"(acc[i4][j]) : "l"(wp[i4]), "l"(xd[j]));
        }

        if (c + 1 < NCHUNK) {
            // publish prefetched chunk c+1 into the OTHER buffer
            float* Wn = smem + ((c + 1) & 1) * BUF_FLOATS;
            float* Xn = Wn + BK * WS_STRIDE;
            #pragma unroll
            for (int it = 0; it < 16; it++) {
                int idx = it * NTHREADS + tid;
                int m   = idx >> 5;
                int kk  = idx & 31;
                Wn[kk * WS_STRIDE + m] = wreg[it];
            }
            #pragma unroll
            for (int it = 0; it < 4; it++) {
                int idx = it * NTHREADS + tid;
                int kk  = idx >> 5;
                int sub = idx & 31;
                int wl  = sub & 1;
                int h   = sub >> 1;
                Xn[kk * XS_STRIDE + wl * 16 + h] = xreg[it];
            }
            // prefetch chunk c+2 into registers
            if (c + 2 < NCHUNK) {
                int kc = (c + 2) * BK;
                #pragma unroll
                for (int it = 0; it < 16; it++) {
                    int idx = it * NTHREADS + tid;
                    int m   = idx >> 5;
                    int kk  = idx & 31;
                    wreg[it] = (m < M_FEAT) ? depth_w[m * CAM_C + kc + kk] : 0.f;
                }
                #pragma unroll
                for (int it = 0; it < 4; it++) {
                    int idx = it * NTHREADS + tid;
                    int kk  = idx >> 5;
                    int sub = idx & 31;
                    int wl  = sub & 1;
                    int h   = sub >> 1;
                    xreg[it] = xcam[(size_t)(kc + kk) * HW + h * FW + w0 + wl];
                }
            }
            __syncthreads();   // single sync per chunk
        }
    }
    // phase 2 writes only buf0 sub-region, disjoint from buf1 (chunk 7) reads.

    // --- phase 2: unpack accs (+bias) into depthS / ctxS ---
    float* depthS = smem;                     // [np][61]
    float* ctxS   = smem + BN * DS_STRIDE;    // [np][68]

    #pragma unroll
    for (int i4 = 0; i4 < 2; i4++) {
        int m0 = tm * 4 + 2 * i4;
        float b0 = (m0     < M_FEAT) ? depth_b[m0]     : 0.f;
        float b1 = (m0 + 1 < M_FEAT) ? depth_b[m0 + 1] : 0.f;
        #pragma unroll
        for (int j = 0; j < 4; j++) {
            float lo, hi;
            asm("mov.b64 {%0, %1}, %2;" : "=f"(lo), "=f"(hi) : "l"(acc[i4][j]));
            int pix = tn * 4 + j;
            float v0 = lo + b0, v1 = hi + b1;
            if (m0 < D_BINS)       depthS[pix * DS_STRIDE + m0] = v0;
            else if (m0 < M_FEAT)  ctxS[pix * CS_STRIDE + (m0 - D_BINS)] = v0;
            int m1 = m0 + 1;
            if (m1 < D_BINS)       depthS[pix * DS_STRIDE + m1] = v1;
            else if (m1 < M_FEAT)  ctxS[pix * CS_STRIDE + (m1 - D_BINS)] = v1;
        }
    }
    __syncthreads();

    const float c00 = comb[0], c01 = comb[1], c02 = comb[2];
    const float c10 = comb[3], c11 = comb[4], c12 = comb[5];
    const float c20 = comb[6], c21 = comb[7], c22 = comb[8];
    const float t0 = tr[0], t1 = tr[1], t2 = tr[2];
    const float xstep = 703.0f / 43.0f;
    const float ystep = 255.0f / 15.0f;
    const int   fast  = s_fast;
    const int   ep    = s_ep;

    // --- softmax: 8 lanes per pixel, shfl reductions; zero z-invalid bins ---
    {
        int pix = tid >> 3;          // 0..31
        int sub = tid & 7;           // 0..7
        float* row = depthS + pix * DS_STRIDE;

        float mx = -1e30f;
        for (int d = sub; d < D_BINS; d += 8) mx = fmaxf(mx, row[d]);
        #pragma unroll
        for (int o = 1; o < 8; o <<= 1)
            mx = fmaxf(mx, __shfl_xor_sync(0xffffffffu, mx, o));

        float s = 0.f;
        for (int d = sub; d < D_BINS; d += 8) {
            float e = __expf(row[d] - mx);
            row[d] = e;
            s += e;
        }
        #pragma unroll
        for (int o = 1; o < 8; o <<= 1)
            s += __shfl_xor_sync(0xffffffffu, s, o);
        float invs = 1.0f / s;

        if (fast) {
            int wl = pix >> 4, h = pix & 15;
            float xim = (float)(w0 + wl) * xstep;
            float yim = (float)h * ystep;
            for (int d = sub; d < D_BINS; d += 8) {
                float ds = 1.0f + (float)d;
                float gz = c20 * (xim * ds) + c21 * (yim * ds) + c22 * ds + t2;
                int cz = (int)floorf((gz + 10.0f) / 20.0f);
                row[d] = (cz == 0) ? row[d] * invs : 0.f;
            }
        } else {
            for (int d = sub; d < D_BINS; d += 8) row[d] *= invs;
        }
    }
    __syncthreads();   // publish softmax; active buffer pre-zeroed last launch

    float* base = g_scratch + (size_t)(ep & 1) * SCR_SZ
                            + (size_t)b * NCELL * OUT_C;

    if (fast) {
        // --- fast combine+scatter: warp = (wl, 16-depth chunk);
        //     lane = (dloc, channel-half). ctx broadcast, accs in registers.
        const int warp  = tid >> 5;           // 0..7
        const int lane  = tid & 31;
        const int wl    = warp & 1;
        const int d0    = (warp >> 1) * 16;   // 0,16,32,48
        const int dloc  = lane >> 1;          // 0..15
        const int d     = d0 + dloc;
        const int chalf = lane & 1;           // channels chalf*32 .. +31
        const bool dok  = (d < D_BINS);

        float ds  = 1.0f + (float)d;
        float xim = (float)(w0 + wl) * xstep;
        float gx = c00 * (xim * ds) + c02 * ds + t0;   // c01 exactly 0
        float gy = c10 * (xim * ds) + c12 * ds + t1;   // c11 exactly 0
        int cx = (int)floorf((gx + 51.2f) / 0.8f);
        int cy = (int)floorf((gy + 51.2f) / 0.8f);
        bool ok = dok && ((unsigned)cx < (unsigned)NX) && ((unsigned)cy < (unsigned)NY);

        ull v[16];                              // 8 float4 accumulators
        #pragma unroll
        for (int j = 0; j < 16; j++) v[j] = 0ull;
        float dwsum = 0.f;

        const float* drow0 = depthS + (wl * 16) * DS_STRIDE;
        const float* crow0 = ctxS   + (wl * 16) * CS_STRIDE + chalf * 32;

        #pragma unroll
        for (int h = 0; h < 16; h++) {
            float dw = dok ? drow0[h * DS_STRIDE + d] : 0.f;
            dwsum += dw;
            ull dw2; asm("mov.b64 %0, {%1, %1};" : "=l"(dw2) : "f"(dw));
            const float* cr = crow0 + h * CS_STRIDE;
            #pragma unroll
            for (int q = 0; q < 8; q++) {
                float4 cc = *(const float4*)(cr + q * 4);   // warp-broadcast
                ull lo, hi;
                asm("mov.b64 %0, {%1, %2};" : "=l"(lo) : "f"(cc.x), "f"(cc.y));
                asm("mov.b64 %0, {%1, %2};" : "=l"(hi) : "f"(cc.z), "f"(cc.w));
                asm("fma.rn.f32x2 %0, %1, %2, %0;" : "+l"(v[2*q  ]) : "l"(lo), "l"(dw2));
                asm("fma.rn.f32x2 %0, %1, %2, %0;" : "+l"(v[2*q+1]) : "l"(hi), "l"(dw2));
            }
        }

        if (ok && dwsum != 0.f) {
            float* dst = base + ((size_t)cy * NX + cx) * OUT_C + chalf * 32;
            #pragma unroll
            for (int q = 0; q < 8; q++) {
                float f0, f1, f2, f3;
                asm("mov.b64 {%0, %1}, %2;" : "=f"(f0), "=f"(f1) : "l"(v[2*q  ]));
                asm("mov.b64 {%0, %1}, %2;" : "=f"(f2), "=f"(f3) : "l"(v[2*q+1]));
                asm volatile("red.global.add.v4.f32 [%0], {%1, %2, %3, %4};"
                             :: "l"(dst + q * 4),
                                "f"(f0), "f"(f1), "f"(f2), "f"(f3) : "memory");
            }
        }
    } else {
        // --- generic fallback: per-point scatter (any geometry) ---
        for (int idx = tid; idx < BN * D_BINS; idx += NTHREADS) {
            int np = idx / D_BINS;
            int d  = idx - np * D_BINS;
            int wl = np >> 4, h = np & 15;
            float ds  = 1.0f + (float)d;
            float xim = (float)(w0 + wl) * xstep;
            float yim = (float)h * ystep;
            float px = xim * ds, py = yim * ds, pz = ds;
            float gx = c00 * px + c01 * py + c02 * pz + t0;
            float gy = c10 * px + c11 * py + c12 * pz + t1;
            float gz = c20 * px + c21 * py + c22 * pz + t2;
            int cx = (int)floorf((gx + 51.2f) / 0.8f);
            int cy = (int)floorf((gy + 51.2f) / 0.8f);
            int cz = (int)floorf((gz + 10.0f) / 20.0f);
            if (((unsigned)cx < (unsigned)NX) && ((unsigned)cy < (unsigned)NY) && cz == 0) {
                float dwgt = depthS[np * DS_STRIDE + d];
                float* dst = base + ((size_t)cy * NX + cx) * OUT_C;
                const float4* cv = (const float4*)(ctxS + np * CS_STRIDE);
                #pragma unroll
                for (int c4 = 0; c4 < OUT_C / 4; c4++) {
                    float4 v = cv[c4];
                    asm volatile("red.global.add.v4.f32 [%0], {%1, %2, %3, %4};"
                                 :: "l"(dst + c4 * 4),
                                    "f"(v.x * dwgt), "f"(v.y * dwgt),
                                    "f"(v.z * dwgt), "f"(v.w * dwgt) : "memory");
                }
            }
        }
    }
    // kernel ends: reds drain behind the kernel boundary; the next kernel in
    // the stream observes them (CUDA kernel-boundary ordering).
}

// ------------- kernel 2: transpose + zero-other + epoch bump ---------------
// 1024 blocks x 128 threads: 32-cell tiles, loads issued before zero-stores.
__global__ __launch_bounds__(128, 8)
void transpose_bev_kernel(float* __restrict__ out)
{
    __shared__ float tile[OUT_C][TCELLS + 1];   // 64 x 33
    __shared__ int   s_ep;
    const int tid = threadIdx.x;            // 128
    const int t   = blockIdx.x;             // tile id 0..1023

    if (tid == 0) s_ep = *(volatile int*)&g_epoch;
    __syncthreads();
    const int ep = s_ep;
    const float* scrA = g_scratch + (size_t)(ep & 1) * SCR_SZ;       // read
    float*       scrB = g_scratch + (size_t)((ep + 1) & 1) * SCR_SZ; // zero

    const int bz    = t >> 9;               // t / 512
    const int cell0 = (t & 511) * TCELLS;
    const float* src = scrA + ((size_t)bz * NCELL + cell0) * OUT_C;

    // 1) issue the 4 independent tile loads FIRST (maximal MLP, front-batched)
    float4 v0, v1, v2, v3;
    {
        int idx0 = 0 * 128 + tid, idx1 = 1 * 128 + tid,
            idx2 = 2 * 128 + tid, idx3 = 3 * 128 + tid;
        v0 = *(const float4*)&src[(idx0 >> 4) * OUT_C + (idx0 & 15) * 4];
        v1 = *(const float4*)&src[(idx1 >> 4) * OUT_C + (idx1 & 15) * 4];
        v2 = *(const float4*)&src[(idx2 >> 4) * OUT_C + (idx2 & 15) * 4];
        v3 = *(const float4*)&src[(idx3 >> 4) * OUT_C + (idx3 & 15) * 4];
    }

    // 2) zero this block's 1/1024 slice of next launch's buffer (fire & forget,
    //    drains behind the loads above)
    {
        float4* p = (float4*)scrB + (size_t)t * (SCR_SZ / 4 / NTILES);
        const float4 z4 = make_float4(0.f, 0.f, 0.f, 0.f);
        #pragma unroll
        for (int i = 0; i < (SCR_SZ / 4 / NTILES) / 128; i++)   // 4 per thread
            p[i * 128 + tid] = z4;
    }

    // 3) stage transposed into smem
    {
        int idx, cell, c4;
        idx = 0 * 128 + tid; cell = idx >> 4; c4 = idx & 15;
        tile[c4*4+0][cell] = v0.x; tile[c4*4+1][cell] = v0.y;
        tile[c4*4+2][cell] = v0.z; tile[c4*4+3][cell] = v0.w;
        idx = 1 * 128 + tid; cell = idx >> 4; c4 = idx & 15;
        tile[c4*4+0][cell] = v1.x; tile[c4*4+1][cell] = v1.y;
        tile[c4*4+2][cell] = v1.z; tile[c4*4+3][cell] = v1.w;
        idx = 2 * 128 + tid; cell = idx >> 4; c4 = idx & 15;
        tile[c4*4+0][cell] = v2.x; tile[c4*4+1][cell] = v2.y;
        tile[c4*4+2][cell] = v2.z; tile[c4*4+3][cell] = v2.w;
        idx = 3 * 128 + tid; cell = idx >> 4; c4 = idx & 15;
        tile[c4*4+0][cell] = v3.x; tile[c4*4+1][cell] = v3.y;
        tile[c4*4+2][cell] = v3.z; tile[c4*4+3][cell] = v3.w;
    }
    __syncthreads();

    // 4) coalesced output stores: 64 ch x 8 float4 rows
    #pragma unroll
    for (int i = 0; i < 4; i++) {
        int idx = i * 128 + tid;            // 0..511
        int ch  = idx >> 3;                 // 0..63
        int seg = idx & 7;                  // 0..7 (8 float4 per ch)
        float4 v = make_float4(tile[ch][seg * 4 + 0], tile[ch][seg * 4 + 1],
                               tile[ch][seg * 4 + 2], tile[ch][seg * 4 + 3]);
        *(float4*)&out[((size_t)(bz * OUT_C + ch)) * NCELL + cell0 + seg * 4] = v;
    }

    // epoch bump: last block to take a ticket advances the epoch (monotonic,
    // replay-safe; all blocks read g_epoch before taking their ticket).
    if (tid == 0) {
        int tk = atomicAdd(&g_cnt_tr, 1);
        if ((tk % NTILES) == NTILES - 1)
            *(volatile int*)&g_epoch = ep + 1;
    }
}

// ---------------- launch ----------------
extern "C" void kernel_launch(void* const* d_in, const int* in_sizes, int n_in,
                              void* d_out, int out_size)
{
    const float* x       = (const float*)d_in[0];
    const float* rots    = (const float*)d_in[1];
    const float* trans   = (const float*)d_in[2];
    const float* intrins = (const float*)d_in[3];
    const float* depth_w = (const float*)d_in[4];
    const float* depth_b = (const float*)d_in[5];
    float* out = (float*)d_out;

    // kernel 1: GEMM + softmax + scatter (reds posted; drain over boundary)
    {
        dim3 grid(FW / WCOLS, CAMS);   // (22, 12) = 264 blocks
        lss_fused_kernel<<<grid, NTHREADS>>>(x, rots, trans, intrins,
                                             depth_w, depth_b);
    }
    // kernel 2: transpose to (B, C, NY, NX) + zero other buffer + epoch bump
    transpose_bev_kernel<<<NTILES, 128>>>(out);

    (void)in_sizes; (void)n_in; (void)out_size;
}